// round 1
// baseline (speedup 1.0000x reference)
#include <cuda_runtime.h>

#define NN 50000
#define NE 800000
#define CDIM 128
#define DIN 32
#define TT0 25000
#define NOUT 16

// ---- scratch (static device globals; no allocation allowed) ----
__device__ float g_x[NN * CDIM];
__device__ float g_y[NN * CDIM];
__device__ float g_agg[NN * CDIM];
__device__ int   g_cnt[NN];
__device__ int   g_fill[NN];
__device__ int   g_ptr[NN + 1];
__device__ int   g_src[NE];

// ---------------------------------------------------------------
__global__ void zero_kernel() {
    int i = blockIdx.x * blockDim.x + threadIdx.x;
    if (i < NN) { g_cnt[i] = 0; g_fill[i] = 0; }
}

__global__ void hist_kernel(const int* __restrict__ ei) {
    int e = blockIdx.x * blockDim.x + threadIdx.x;
    if (e < NE) atomicAdd(&g_cnt[ei[NE + e]], 1);
}

// single-block exclusive scan of g_cnt -> g_ptr (50000 elems)
__global__ void scan_kernel() {
    __shared__ int sdata[1024];
    __shared__ int s_carry;
    int tid = threadIdx.x;
    if (tid == 0) s_carry = 0;
    __syncthreads();
    for (int base = 0; base < NN; base += 1024) {
        int i = base + tid;
        int v = (i < NN) ? g_cnt[i] : 0;
        sdata[tid] = v;
        __syncthreads();
        for (int off = 1; off < 1024; off <<= 1) {
            int t = (tid >= off) ? sdata[tid - off] : 0;
            __syncthreads();
            sdata[tid] += t;
            __syncthreads();
        }
        if (i < NN) g_ptr[i] = s_carry + sdata[tid] - v;
        __syncthreads();
        if (tid == 1023) s_carry += sdata[1023];
        __syncthreads();
    }
    if (tid == 0) g_ptr[NN] = s_carry;
}

__global__ void fill_kernel(const int* __restrict__ ei) {
    int e = blockIdx.x * blockDim.x + threadIdx.x;
    if (e < NE) {
        int s = ei[e];
        int d = ei[NE + e];
        int p = atomicAdd(&g_fill[d], 1);
        g_src[g_ptr[d] + p] = s;
    }
}

// ---------------------------------------------------------------
// Fused heterogeneous encode + node gather: g_x[n] = feats[row(n)] @ W + b
__global__ __launch_bounds__(128) void encode_kernel(
    const float* __restrict__ f0, const float* __restrict__ f1,
    const float* __restrict__ w0, const float* __restrict__ b0v,
    const float* __restrict__ w1, const float* __restrict__ b1v,
    const int* __restrict__ row_idx)
{
    __shared__ float sW0[DIN * CDIM];
    __shared__ float sW1[DIN * CDIM];
    __shared__ float sb0[CDIM], sb1[CDIM];
    int tid = threadIdx.x;
    for (int i = tid; i < DIN * CDIM; i += 128) { sW0[i] = w0[i]; sW1[i] = w1[i]; }
    sb0[tid] = b0v[tid];
    sb1[tid] = b1v[tid];
    __syncthreads();

    for (int n = blockIdx.x; n < NN; n += gridDim.x) {
        int r = row_idx[n];
        const float* f;
        const float* sW;
        float acc;
        if (r < TT0) { f = f0 + (size_t)r * DIN;          sW = sW0; acc = sb0[tid]; }
        else         { f = f1 + (size_t)(r - TT0) * DIN;  sW = sW1; acc = sb1[tid]; }
        #pragma unroll
        for (int k = 0; k < DIN; k++)
            acc += f[k] * sW[k * CDIM + tid];
        g_x[(size_t)n * CDIM + tid] = acc;
    }
}

// ---------------------------------------------------------------
// warp-per-node mean aggregation via CSR: g_agg[n] = mean over in-edges of xin[src]
__global__ __launch_bounds__(256) void agg_kernel(const float* __restrict__ xin) {
    int w = (blockIdx.x * blockDim.x + threadIdx.x) >> 5;
    int lane = threadIdx.x & 31;
    if (w >= NN) return;
    int beg = g_ptr[w], end = g_ptr[w + 1];
    float4 acc = make_float4(0.f, 0.f, 0.f, 0.f);
    for (int e = beg; e < end; e++) {
        int s = g_src[e];
        float4 v = *reinterpret_cast<const float4*>(xin + (size_t)s * CDIM + lane * 4);
        acc.x += v.x; acc.y += v.y; acc.z += v.z; acc.w += v.w;
    }
    float inv = 1.0f / fmaxf((float)(end - beg), 1.0f);
    acc.x *= inv; acc.y *= inv; acc.z *= inv; acc.w *= inv;
    *reinterpret_cast<float4*>(g_agg + (size_t)w * CDIM + lane * 4) = acc;
}

// ---------------------------------------------------------------
// Y = A1 @ B1 + A2 @ B2 + bias (one virtual GEMM, K=256), optional ReLU.
// BM=128, BN=128, BK=16, 256 threads, 8x8 register tiles.
template <bool RELU>
__global__ __launch_bounds__(256) void combine_kernel(
    const float* __restrict__ A1, const float* __restrict__ A2,
    const float* __restrict__ B1, const float* __restrict__ B2,
    const float* __restrict__ bias, float* __restrict__ Y)
{
    __shared__ float As[16][136];   // [k][row], padded
    __shared__ float Bs[16][128];   // [k][col]

    int tid = threadIdx.x;
    int tx = tid & 15;          // col group
    int ty = tid >> 4;          // row group
    int row0 = blockIdx.x * 128;

    float acc[8][8];
    #pragma unroll
    for (int i = 0; i < 8; i++)
        #pragma unroll
        for (int j = 0; j < 8; j++) acc[i][j] = 0.f;

    #pragma unroll 1
    for (int kb = 0; kb < 16; kb++) {
        const float* A = (kb < 8) ? A1 : A2;
        const float* B = (kb < 8) ? B1 : B2;
        int koff = (kb & 7) * 16;

        // load A tile (128 rows x 16 k), transpose into As[k][row]
        #pragma unroll
        for (int p = 0; p < 2; p++) {
            int idx = tid + p * 256;          // 512 float4s
            int r = idx >> 2;
            int c4 = (idx & 3) * 4;
            float4 v = make_float4(0.f, 0.f, 0.f, 0.f);
            if (row0 + r < NN)
                v = *reinterpret_cast<const float4*>(A + (size_t)(row0 + r) * CDIM + koff + c4);
            As[c4 + 0][r] = v.x;
            As[c4 + 1][r] = v.y;
            As[c4 + 2][r] = v.z;
            As[c4 + 3][r] = v.w;
        }
        // load B tile (16 k x 128 cols)
        #pragma unroll
        for (int p = 0; p < 2; p++) {
            int idx = tid + p * 256;          // 512 float4s
            int k = idx >> 5;
            int c = (idx & 31) * 4;
            *reinterpret_cast<float4*>(&Bs[k][c]) =
                *reinterpret_cast<const float4*>(B + (size_t)(koff + k) * CDIM + c);
        }
        __syncthreads();

        #pragma unroll
        for (int k = 0; k < 16; k++) {
            float4 a0 = *reinterpret_cast<const float4*>(&As[k][ty * 8]);
            float4 a1 = *reinterpret_cast<const float4*>(&As[k][ty * 8 + 4]);
            float4 b0 = *reinterpret_cast<const float4*>(&Bs[k][tx * 8]);
            float4 b1 = *reinterpret_cast<const float4*>(&Bs[k][tx * 8 + 4]);
            float ar[8] = {a0.x, a0.y, a0.z, a0.w, a1.x, a1.y, a1.z, a1.w};
            float br[8] = {b0.x, b0.y, b0.z, b0.w, b1.x, b1.y, b1.z, b1.w};
            #pragma unroll
            for (int i = 0; i < 8; i++)
                #pragma unroll
                for (int j = 0; j < 8; j++)
                    acc[i][j] += ar[i] * br[j];
        }
        __syncthreads();
    }

    // epilogue
    float bv[8];
    #pragma unroll
    for (int j = 0; j < 8; j++) bv[j] = bias[tx * 8 + j];

    #pragma unroll
    for (int i = 0; i < 8; i++) {
        int row = row0 + ty * 8 + i;
        if (row < NN) {
            float4 o0, o1;
            float v0 = acc[i][0] + bv[0], v1 = acc[i][1] + bv[1];
            float v2 = acc[i][2] + bv[2], v3 = acc[i][3] + bv[3];
            float v4 = acc[i][4] + bv[4], v5 = acc[i][5] + bv[5];
            float v6 = acc[i][6] + bv[6], v7 = acc[i][7] + bv[7];
            if (RELU) {
                v0 = fmaxf(v0, 0.f); v1 = fmaxf(v1, 0.f); v2 = fmaxf(v2, 0.f); v3 = fmaxf(v3, 0.f);
                v4 = fmaxf(v4, 0.f); v5 = fmaxf(v5, 0.f); v6 = fmaxf(v6, 0.f); v7 = fmaxf(v7, 0.f);
            }
            o0 = make_float4(v0, v1, v2, v3);
            o1 = make_float4(v4, v5, v6, v7);
            *reinterpret_cast<float4*>(Y + (size_t)row * CDIM + tx * 8)     = o0;
            *reinterpret_cast<float4*>(Y + (size_t)row * CDIM + tx * 8 + 4) = o1;
        }
    }
}

// ---------------------------------------------------------------
// head: out = x @ head_w + head_b,  [NN,128] @ [128,16]
__global__ __launch_bounds__(256) void head_kernel(
    const float* __restrict__ xin, const float* __restrict__ hw,
    const float* __restrict__ hb, float* __restrict__ out)
{
    __shared__ float sw[CDIM * NOUT];
    __shared__ float sb[NOUT];
    __shared__ float xs[16][CDIM];
    int tid = threadIdx.x;
    for (int i = tid; i < CDIM * NOUT; i += 256) sw[i] = hw[i];
    if (tid < NOUT) sb[tid] = hb[tid];
    __syncthreads();

    int base = blockIdx.x * 16;
    // stage 16 rows of x
    #pragma unroll
    for (int p = 0; p < 2; p++) {
        int idx = tid + p * 256;    // 512 float4
        int r = idx >> 5;
        int c = (idx & 31) * 4;
        float4 v = make_float4(0.f, 0.f, 0.f, 0.f);
        if (base + r < NN)
            v = *reinterpret_cast<const float4*>(xin + (size_t)(base + r) * CDIM + c);
        *reinterpret_cast<float4*>(&xs[r][c]) = v;
    }
    __syncthreads();

    int n = tid >> 4;       // 0..15
    int o = tid & 15;       // 0..15
    float acc = sb[o];
    #pragma unroll
    for (int k = 0; k < CDIM; k++)
        acc += xs[n][k] * sw[k * NOUT + o];
    if (base + n < NN)
        out[(size_t)(base + n) * NOUT + o] = acc;
}

// ---------------------------------------------------------------
extern "C" void kernel_launch(void* const* d_in, const int* in_sizes, int n_in,
                              void* d_out, int out_size)
{
    const float* feats0  = (const float*)d_in[0];
    const float* feats1  = (const float*)d_in[1];
    const float* enc_w0  = (const float*)d_in[2];
    const float* enc_b0  = (const float*)d_in[3];
    const float* enc_w1  = (const float*)d_in[4];
    const float* enc_b1  = (const float*)d_in[5];
    const float* w_self0 = (const float*)d_in[6];
    const float* w_neigh0= (const float*)d_in[7];
    const float* b0      = (const float*)d_in[8];
    const float* w_self1 = (const float*)d_in[9];
    const float* w_neigh1= (const float*)d_in[10];
    const float* b1      = (const float*)d_in[11];
    const float* head_w  = (const float*)d_in[12];
    const float* head_b  = (const float*)d_in[13];
    const int*   row_idx = (const int*)d_in[14];
    const int*   edge_ix = (const int*)d_in[15];
    float* out = (float*)d_out;

    float* gx;  cudaGetSymbolAddress((void**)&gx,  g_x);
    float* gy;  cudaGetSymbolAddress((void**)&gy,  g_y);
    float* ga;  cudaGetSymbolAddress((void**)&ga,  g_agg);

    // CSR build
    zero_kernel<<<(NN + 255) / 256, 256>>>();
    hist_kernel<<<(NE + 255) / 256, 256>>>(edge_ix);
    scan_kernel<<<1, 1024>>>();
    fill_kernel<<<(NE + 255) / 256, 256>>>(edge_ix);

    // encode (fused gather)
    encode_kernel<<<888, 128>>>(feats0, feats1, enc_w0, enc_b0, enc_w1, enc_b1, row_idx);

    int agg_blocks = (NN * 32 + 255) / 256;
    int gemm_blocks = (NN + 127) / 128;

    // layer 0
    agg_kernel<<<agg_blocks, 256>>>(gx);
    combine_kernel<true><<<gemm_blocks, 256>>>(gx, ga, w_self0, w_neigh0, b0, gy);
    // layer 1
    agg_kernel<<<agg_blocks, 256>>>(gy);
    combine_kernel<false><<<gemm_blocks, 256>>>(gy, ga, w_self1, w_neigh1, b1, gx);

    // head
    head_kernel<<<(NN + 15) / 16, 256>>>(gx, head_w, head_b, out);
}

// round 2
// speedup vs baseline: 1.1532x; 1.1532x over previous
#include <cuda_runtime.h>

#define NN 50000
#define NE 800000
#define CDIM 128
#define DIN 32
#define TT0 25000
#define NOUT 16

// ---- scratch (static device globals; no allocation allowed) ----
__device__ float g_x[NN * CDIM];        // node features (x0, then reused for x1)
__device__ float g_U[NN * 256];         // layer-1 GEMM output [self | neigh]
__device__ float g_V[NN * 32];          // layer-2 folded GEMM output [self16 | neigh16]
__device__ float g_wc[CDIM * 32];       // folded weights [k][0..15 self, 16..31 neigh]
__device__ float g_bc[NOUT];            // folded bias
__device__ int   g_cnt[NN];
__device__ int   g_fill[NN];            // fill cursor (init to ptr by scan)
__device__ int   g_ptr[NN + 1];
__device__ int   g_src[NE];

// ---------------------------------------------------------------
__global__ void hist_kernel(const int* __restrict__ ei) {
    int i = blockIdx.x * blockDim.x + threadIdx.x;
    if (i < NE / 4) {
        int4 d = reinterpret_cast<const int4*>(ei + NE)[i];
        atomicAdd(&g_cnt[d.x], 1);
        atomicAdd(&g_cnt[d.y], 1);
        atomicAdd(&g_cnt[d.z], 1);
        atomicAdd(&g_cnt[d.w], 1);
    }
}

// single-block thread-coarsened exclusive scan: g_cnt -> g_ptr, g_fill
__global__ __launch_bounds__(1024) void scan_kernel() {
    const int CH = (NN + 1023) / 1024;   // 49
    int t = threadIdx.x;
    int beg = t * CH;
    int end = min(beg + CH, NN);
    int s = 0;
    for (int i = beg; i < end; i++) s += g_cnt[i];

    int lane = t & 31, wid = t >> 5;
    int v = s;
    #pragma unroll
    for (int o = 1; o < 32; o <<= 1) {
        int u = __shfl_up_sync(0xffffffffu, v, o);
        if (lane >= o) v += u;
    }
    __shared__ int wsum[32];
    if (lane == 31) wsum[wid] = v;
    __syncthreads();
    if (wid == 0) {
        int w = wsum[lane];
        #pragma unroll
        for (int o = 1; o < 32; o <<= 1) {
            int u = __shfl_up_sync(0xffffffffu, w, o);
            if (lane >= o) w += u;
        }
        wsum[lane] = w;
    }
    __syncthreads();
    int excl = v - s + (wid ? wsum[wid - 1] : 0);
    int run = excl;
    for (int i = beg; i < end; i++) {
        int c = g_cnt[i];
        g_ptr[i] = run;
        g_fill[i] = run;
        run += c;
    }
    if (t == 1023) g_ptr[NN] = run;
}

__global__ void fill_kernel(const int* __restrict__ ei) {
    int e = blockIdx.x * blockDim.x + threadIdx.x;
    if (e < NE) {
        int s = ei[e];
        int d = ei[NE + e];
        int pos = atomicAdd(&g_fill[d], 1);
        g_src[pos] = s;
    }
}

// ---------------------------------------------------------------
// Fused heterogeneous encode + node gather: g_x[n] = feats[row(n)] @ W + b
__global__ __launch_bounds__(128) void encode_kernel(
    const float* __restrict__ f0, const float* __restrict__ f1,
    const float* __restrict__ w0, const float* __restrict__ b0v,
    const float* __restrict__ w1, const float* __restrict__ b1v,
    const int* __restrict__ row_idx)
{
    __shared__ float sW0[DIN * CDIM];
    __shared__ float sW1[DIN * CDIM];
    __shared__ float sb0[CDIM], sb1[CDIM];
    int tid = threadIdx.x;
    for (int i = tid; i < DIN * CDIM; i += 128) { sW0[i] = w0[i]; sW1[i] = w1[i]; }
    sb0[tid] = b0v[tid];
    sb1[tid] = b1v[tid];
    __syncthreads();

    for (int n = blockIdx.x; n < NN; n += gridDim.x) {
        int r = row_idx[n];
        const float* f;
        const float* sW;
        float acc;
        if (r < TT0) { f = f0 + (size_t)r * DIN;          sW = sW0; acc = sb0[tid]; }
        else         { f = f1 + (size_t)(r - TT0) * DIN;  sW = sW1; acc = sb1[tid]; }
        #pragma unroll
        for (int k = 0; k < DIN; k++)
            acc += f[k] * sW[k * CDIM + tid];
        g_x[(size_t)n * CDIM + tid] = acc;
    }
}

// ---------------------------------------------------------------
// GEMM1: U = x @ [Ws | Wn]   (A [NN,128], B half picked by blockIdx.y)
// BM=128, BN=128, BK=16, 256 threads, 8x8 register tiles, double-buffered.
__global__ __launch_bounds__(256) void gemm1_kernel(
    const float* __restrict__ A,
    const float* __restrict__ Bself, const float* __restrict__ Bneigh)
{
    const float* B = blockIdx.y ? Bneigh : Bself;
    int col_off = blockIdx.y * 128;

    __shared__ float As[2][16][136];
    __shared__ float Bs[2][16][132];

    int tid = threadIdx.x;
    int tx = tid & 15;
    int ty = tid >> 4;
    int row0 = blockIdx.x * 128;

    float acc[8][8];
    #pragma unroll
    for (int i = 0; i < 8; i++)
        #pragma unroll
        for (int j = 0; j < 8; j++) acc[i][j] = 0.f;

    auto loadA = [&](int kb, int buf) {
        #pragma unroll
        for (int p = 0; p < 2; p++) {
            int idx = tid + p * 256;
            int r = idx >> 2;
            int c4 = (idx & 3) * 4;
            float4 v = make_float4(0.f, 0.f, 0.f, 0.f);
            if (row0 + r < NN)
                v = *reinterpret_cast<const float4*>(A + (size_t)(row0 + r) * CDIM + kb * 16 + c4);
            As[buf][c4 + 0][r] = v.x;
            As[buf][c4 + 1][r] = v.y;
            As[buf][c4 + 2][r] = v.z;
            As[buf][c4 + 3][r] = v.w;
        }
    };
    auto loadB = [&](int kb, int buf) {
        #pragma unroll
        for (int p = 0; p < 2; p++) {
            int idx = tid + p * 256;
            int k = idx >> 5;
            int c = (idx & 31) * 4;
            *reinterpret_cast<float4*>(&Bs[buf][k][c]) =
                *reinterpret_cast<const float4*>(B + (size_t)(kb * 16 + k) * CDIM + c);
        }
    };

    loadA(0, 0);
    loadB(0, 0);
    __syncthreads();

    #pragma unroll 1
    for (int kb = 0; kb < 8; kb++) {
        int buf = kb & 1;
        if (kb < 7) { loadA(kb + 1, buf ^ 1); loadB(kb + 1, buf ^ 1); }
        #pragma unroll
        for (int k = 0; k < 16; k++) {
            float4 a0 = *reinterpret_cast<const float4*>(&As[buf][k][ty * 8]);
            float4 a1 = *reinterpret_cast<const float4*>(&As[buf][k][ty * 8 + 4]);
            float4 b0 = *reinterpret_cast<const float4*>(&Bs[buf][k][tx * 8]);
            float4 b1 = *reinterpret_cast<const float4*>(&Bs[buf][k][tx * 8 + 4]);
            float ar[8] = {a0.x, a0.y, a0.z, a0.w, a1.x, a1.y, a1.z, a1.w};
            float br[8] = {b0.x, b0.y, b0.z, b0.w, b1.x, b1.y, b1.z, b1.w};
            #pragma unroll
            for (int i = 0; i < 8; i++)
                #pragma unroll
                for (int j = 0; j < 8; j++)
                    acc[i][j] += ar[i] * br[j];
        }
        __syncthreads();
    }

    #pragma unroll
    for (int i = 0; i < 8; i++) {
        int row = row0 + ty * 8 + i;
        if (row < NN) {
            *reinterpret_cast<float4*>(g_U + (size_t)row * 256 + col_off + tx * 8) =
                make_float4(acc[i][0], acc[i][1], acc[i][2], acc[i][3]);
            *reinterpret_cast<float4*>(g_U + (size_t)row * 256 + col_off + tx * 8 + 4) =
                make_float4(acc[i][4], acc[i][5], acc[i][6], acc[i][7]);
        }
    }
}

// ---------------------------------------------------------------
// agg1: x1[n] = relu(U_self[n] + mean_src U_neigh[src] + b0)   (warp per node)
__global__ __launch_bounds__(256) void agg1_kernel(const float* __restrict__ b0v,
                                                   float* __restrict__ xout)
{
    int w = (blockIdx.x * blockDim.x + threadIdx.x) >> 5;
    int lane = threadIdx.x & 31;
    if (w >= NN) return;
    int beg = g_ptr[w], end = g_ptr[w + 1];
    float4 acc = make_float4(0.f, 0.f, 0.f, 0.f);
    for (int e = beg; e < end; e++) {
        int s = g_src[e];
        float4 v = *reinterpret_cast<const float4*>(g_U + (size_t)s * 256 + 128 + lane * 4);
        acc.x += v.x; acc.y += v.y; acc.z += v.z; acc.w += v.w;
    }
    float inv = 1.0f / fmaxf((float)(end - beg), 1.0f);
    float4 self = *reinterpret_cast<const float4*>(g_U + (size_t)w * 256 + lane * 4);
    float4 b = *reinterpret_cast<const float4*>(b0v + lane * 4);
    float4 o;
    o.x = fmaxf(self.x + acc.x * inv + b.x, 0.f);
    o.y = fmaxf(self.y + acc.y * inv + b.y, 0.f);
    o.z = fmaxf(self.z + acc.z * inv + b.z, 0.f);
    o.w = fmaxf(self.w + acc.w * inv + b.w, 0.f);
    *reinterpret_cast<float4*>(xout + (size_t)w * CDIM + lane * 4) = o;
}

// ---------------------------------------------------------------
// fold: Wc = [Ws1 @ Hw | Wn1 @ Hw] (layout [k][32]), bc = b1 @ Hw + Hb
__global__ __launch_bounds__(512) void fold_kernel(
    const float* __restrict__ ws1, const float* __restrict__ wn1,
    const float* __restrict__ b1v,
    const float* __restrict__ hw, const float* __restrict__ hb)
{
    __shared__ float sH[CDIM * NOUT];
    int tid = threadIdx.x;
    for (int i = tid; i < CDIM * NOUT; i += 512) sH[i] = hw[i];
    __syncthreads();

    for (int idx = tid; idx < CDIM * 32; idx += 512) {
        int half = (idx >> 4) & 1;          // 0: self, 1: neigh
        int k = idx >> 5;                   // 0..127
        int j = idx & 15;                   // 0..15
        const float* W = half ? wn1 : ws1;
        float acc = 0.f;
        #pragma unroll 8
        for (int c = 0; c < CDIM; c++)
            acc += W[k * CDIM + c] * sH[c * NOUT + j];
        g_wc[k * 32 + half * 16 + j] = acc;
    }
    if (tid < NOUT) {
        float acc = hb[tid];
        for (int c = 0; c < CDIM; c++)
            acc += b1v[c] * sH[c * NOUT + tid];
        g_bc[tid] = acc;
    }
}

// ---------------------------------------------------------------
// GEMM2: V = x1 @ Wc   ([NN,128] @ [128,32]); 64 rows per block
__global__ __launch_bounds__(256) void gemm2_kernel(const float* __restrict__ A)
{
    __shared__ float ws[CDIM * 32];         // [k][c]
    __shared__ float xs[64][132];           // padded
    int tid = threadIdx.x;
    for (int i = tid; i < CDIM * 32; i += 256) ws[i] = g_wc[i];

    int base = blockIdx.x * 64;
    // stage 64 rows of x1 (64*32 float4 = 2048)
    #pragma unroll
    for (int p = 0; p < 8; p++) {
        int idx = tid + p * 256;
        int r = idx >> 5;
        int c = (idx & 31) * 4;
        float4 v = make_float4(0.f, 0.f, 0.f, 0.f);
        if (base + r < NN)
            v = *reinterpret_cast<const float4*>(A + (size_t)(base + r) * CDIM + c);
        *reinterpret_cast<float4*>(&xs[r][c]) = v;
    }
    __syncthreads();

    int row = tid >> 2;              // 0..63
    int colg = (tid & 3) * 8;        // 0,8,16,24
    float acc[8];
    #pragma unroll
    for (int j = 0; j < 8; j++) acc[j] = 0.f;
    #pragma unroll 4
    for (int k = 0; k < CDIM; k++) {
        float xv = xs[row][k];
        #pragma unroll
        for (int j = 0; j < 8; j++)
            acc[j] += xv * ws[k * 32 + colg + j];
    }
    if (base + row < NN) {
        *reinterpret_cast<float4*>(g_V + (size_t)(base + row) * 32 + colg) =
            make_float4(acc[0], acc[1], acc[2], acc[3]);
        *reinterpret_cast<float4*>(g_V + (size_t)(base + row) * 32 + colg + 4) =
            make_float4(acc[4], acc[5], acc[6], acc[7]);
    }
}

// ---------------------------------------------------------------
// agg2: out[n][j] = V_self[n][j] + mean_src V_neigh[src][j] + bc[j]
// half-warp per node
__global__ __launch_bounds__(256) void agg2_kernel(float* __restrict__ out)
{
    int w = (blockIdx.x * blockDim.x + threadIdx.x) >> 5;
    int lane = threadIdx.x & 31;
    int n = w * 2 + (lane >> 4);
    int j = lane & 15;
    if (n >= NN) return;
    int beg = g_ptr[n], end = g_ptr[n + 1];
    float acc = 0.f;
    for (int e = beg; e < end; e++) {
        int s = g_src[e];
        acc += g_V[(size_t)s * 32 + 16 + j];
    }
    float inv = 1.0f / fmaxf((float)(end - beg), 1.0f);
    out[(size_t)n * NOUT + j] = g_V[(size_t)n * 32 + j] + acc * inv + g_bc[j];
}

// ---------------------------------------------------------------
extern "C" void kernel_launch(void* const* d_in, const int* in_sizes, int n_in,
                              void* d_out, int out_size)
{
    const float* feats0   = (const float*)d_in[0];
    const float* feats1   = (const float*)d_in[1];
    const float* enc_w0   = (const float*)d_in[2];
    const float* enc_b0   = (const float*)d_in[3];
    const float* enc_w1   = (const float*)d_in[4];
    const float* enc_b1   = (const float*)d_in[5];
    const float* w_self0  = (const float*)d_in[6];
    const float* w_neigh0 = (const float*)d_in[7];
    const float* b0       = (const float*)d_in[8];
    const float* w_self1  = (const float*)d_in[9];
    const float* w_neigh1 = (const float*)d_in[10];
    const float* b1       = (const float*)d_in[11];
    const float* head_w   = (const float*)d_in[12];
    const float* head_b   = (const float*)d_in[13];
    const int*   row_idx  = (const int*)d_in[14];
    const int*   edge_ix  = (const int*)d_in[15];
    float* out = (float*)d_out;

    float* gx;   cudaGetSymbolAddress((void**)&gx,   g_x);
    int*   gcnt; cudaGetSymbolAddress((void**)&gcnt, g_cnt);

    // CSR build
    cudaMemsetAsync(gcnt, 0, NN * sizeof(int));
    hist_kernel<<<(NE / 4 + 255) / 256, 256>>>(edge_ix);
    scan_kernel<<<1, 1024>>>();
    fill_kernel<<<(NE + 255) / 256, 256>>>(edge_ix);

    // fold layer2+head weights
    fold_kernel<<<1, 512>>>(w_self1, w_neigh1, b1, head_w, head_b);

    // encode
    encode_kernel<<<1184, 128>>>(feats0, feats1, enc_w0, enc_b0, enc_w1, enc_b1, row_idx);

    // layer 1: U = x0 @ [Ws0 | Wn0]; x1 = relu(self + mean(neigh) + b0)
    dim3 g1((NN + 127) / 128, 2);
    gemm1_kernel<<<g1, 256>>>(gx, w_self0, w_neigh0);
    agg1_kernel<<<(NN * 32 + 255) / 256, 256>>>(b0, gx);

    // layer 2 + head (folded): V = x1 @ Wc; out = self + mean(neigh) + bc
    gemm2_kernel<<<(NN + 63) / 64, 256>>>(gx);
    agg2_kernel<<<(NN * 16 + 255) / 256, 256>>>(out);
}

// round 3
// speedup vs baseline: 1.1812x; 1.0243x over previous
#include <cuda_runtime.h>

#define NN 50000
#define NE 800000
#define CDIM 128
#define DIN 32
#define TT0 25000
#define NOUT 16

// packed fp32x2 FMA: one issue slot, two fp32 FMAs (exact fp32 numerics)
#define FFMA2(acc, a, b) \
    asm("fma.rn.f32x2 %0, %1, %2, %0;" : "+l"(acc) : "l"(a), "l"(b))

// ---- scratch (static device globals; no allocation allowed) ----
__device__ float g_x[NN * CDIM];        // node features (x0, then x1)
__device__ float g_U[NN * 256];         // layer-1 GEMM output [self | neigh]
__device__ float g_V[NN * 32];          // folded layer-2 GEMM output [self16 | neigh16]
__device__ float g_wc[CDIM * 32];       // folded weights [k][0..15 self, 16..31 neigh]
__device__ float g_bc[NOUT];            // folded bias
__device__ int   g_cnt[NN];
__device__ int   g_fill[NN];            // fill cursor (init to ptr by scan)
__device__ int   g_ptr[NN + 1];
__device__ int   g_src[NE];

// ---------------------------------------------------------------
__global__ void hist_kernel(const int* __restrict__ ei) {
    int i = blockIdx.x * blockDim.x + threadIdx.x;
    if (i < NE / 4) {
        int4 d = reinterpret_cast<const int4*>(ei + NE)[i];
        atomicAdd(&g_cnt[d.x], 1);
        atomicAdd(&g_cnt[d.y], 1);
        atomicAdd(&g_cnt[d.z], 1);
        atomicAdd(&g_cnt[d.w], 1);
    }
}

// single-block thread-coarsened exclusive scan: g_cnt -> g_ptr, g_fill
__global__ __launch_bounds__(1024) void scan_kernel() {
    const int CH = (NN + 1023) / 1024;   // 49
    int t = threadIdx.x;
    int beg = t * CH;
    int end = min(beg + CH, NN);
    int s = 0;
    for (int i = beg; i < end; i++) s += g_cnt[i];

    int lane = t & 31, wid = t >> 5;
    int v = s;
    #pragma unroll
    for (int o = 1; o < 32; o <<= 1) {
        int u = __shfl_up_sync(0xffffffffu, v, o);
        if (lane >= o) v += u;
    }
    __shared__ int wsum[32];
    if (lane == 31) wsum[wid] = v;
    __syncthreads();
    if (wid == 0) {
        int w = wsum[lane];
        #pragma unroll
        for (int o = 1; o < 32; o <<= 1) {
            int u = __shfl_up_sync(0xffffffffu, w, o);
            if (lane >= o) w += u;
        }
        wsum[lane] = w;
    }
    __syncthreads();
    int excl = v - s + (wid ? wsum[wid - 1] : 0);
    int run = excl;
    for (int i = beg; i < end; i++) {
        int c = g_cnt[i];
        g_ptr[i] = run;
        g_fill[i] = run;
        run += c;
    }
    if (t == 1023) g_ptr[NN] = run;
}

__global__ void fill_kernel(const int* __restrict__ ei) {
    int e = blockIdx.x * blockDim.x + threadIdx.x;
    if (e < NE) {
        int s = ei[e];
        int d = ei[NE + e];
        int pos = atomicAdd(&g_fill[d], 1);
        g_src[pos] = s;
    }
}

// ---------------------------------------------------------------
// Fused heterogeneous encode + node gather: g_x[n] = feats[row(n)] @ W + b
__global__ __launch_bounds__(128) void encode_kernel(
    const float* __restrict__ f0, const float* __restrict__ f1,
    const float* __restrict__ w0, const float* __restrict__ b0v,
    const float* __restrict__ w1, const float* __restrict__ b1v,
    const int* __restrict__ row_idx)
{
    __shared__ float sW0[DIN * CDIM];
    __shared__ float sW1[DIN * CDIM];
    __shared__ float sb0[CDIM], sb1[CDIM];
    int tid = threadIdx.x;
    for (int i = tid; i < DIN * CDIM; i += 128) { sW0[i] = w0[i]; sW1[i] = w1[i]; }
    sb0[tid] = b0v[tid];
    sb1[tid] = b1v[tid];
    __syncthreads();

    for (int n = blockIdx.x; n < NN; n += gridDim.x) {
        int r = row_idx[n];
        const float* f;
        const float* sW;
        float acc;
        if (r < TT0) { f = f0 + (size_t)r * DIN;          sW = sW0; acc = sb0[tid]; }
        else         { f = f1 + (size_t)(r - TT0) * DIN;  sW = sW1; acc = sb1[tid]; }
        #pragma unroll
        for (int k = 0; k < DIN; k++)
            acc += f[k] * sW[k * CDIM + tid];
        g_x[(size_t)n * CDIM + tid] = acc;
    }
}

// ---------------------------------------------------------------
// GEMM1: U = x @ [Ws | Wn]  (B half picked by blockIdx.y)
// BM=128, BN=128, BK=16, 256 threads, 8x8 register tiles, double-buffered,
// inner product issued as fp32x2 packed FMA (A duplicated in smem).
#define AS_STRIDE 272   // floats per k-row of duplicated A (256 data + 16 pad)
#define BS_STRIDE 132
#define SMEM_GEMM1 ((2 * 16 * AS_STRIDE + 2 * 16 * BS_STRIDE) * 4)

__global__ __launch_bounds__(256) void gemm1_kernel(
    const float* __restrict__ A,
    const float* __restrict__ Bself, const float* __restrict__ Bneigh)
{
    const float* B = blockIdx.y ? Bneigh : Bself;
    int col_off = blockIdx.y * 128;

    extern __shared__ __align__(16) float smem[];
    float (*As_)[16][AS_STRIDE] = (float (*)[16][AS_STRIDE])smem;
    float (*Bs_)[16][BS_STRIDE] = (float (*)[16][BS_STRIDE])(smem + 2 * 16 * AS_STRIDE);

    int tid = threadIdx.x;
    int tx = tid & 15;
    int ty = tid >> 4;
    int row0 = blockIdx.x * 128;

    unsigned long long acc2[8][4];
    #pragma unroll
    for (int i = 0; i < 8; i++)
        #pragma unroll
        for (int j = 0; j < 4; j++) acc2[i][j] = 0ull;

    auto loadA = [&](int kb, int buf) {
        #pragma unroll
        for (int p = 0; p < 2; p++) {
            int idx = tid + p * 256;
            int r = idx >> 2;
            int c4 = (idx & 3) * 4;
            float4 v = make_float4(0.f, 0.f, 0.f, 0.f);
            if (row0 + r < NN)
                v = *reinterpret_cast<const float4*>(A + (size_t)(row0 + r) * CDIM + kb * 16 + c4);
            // duplicated store: row r value at columns 2r, 2r+1
            *reinterpret_cast<float2*>(&As_[buf][c4 + 0][2 * r]) = make_float2(v.x, v.x);
            *reinterpret_cast<float2*>(&As_[buf][c4 + 1][2 * r]) = make_float2(v.y, v.y);
            *reinterpret_cast<float2*>(&As_[buf][c4 + 2][2 * r]) = make_float2(v.z, v.z);
            *reinterpret_cast<float2*>(&As_[buf][c4 + 3][2 * r]) = make_float2(v.w, v.w);
        }
    };
    auto loadB = [&](int kb, int buf) {
        #pragma unroll
        for (int p = 0; p < 2; p++) {
            int idx = tid + p * 256;
            int k = idx >> 5;
            int c = (idx & 31) * 4;
            *reinterpret_cast<float4*>(&Bs_[buf][k][c]) =
                *reinterpret_cast<const float4*>(B + (size_t)(kb * 16 + k) * CDIM + c);
        }
    };

    loadA(0, 0);
    loadB(0, 0);
    __syncthreads();

    #pragma unroll 1
    for (int kb = 0; kb < 8; kb++) {
        int buf = kb & 1;
        if (kb < 7) { loadA(kb + 1, buf ^ 1); loadB(kb + 1, buf ^ 1); }
        #pragma unroll
        for (int k = 0; k < 16; k++) {
            // duplicated A pairs: (a_i, a_i) each, 4x LDS.128
            ulonglong2 av0 = *reinterpret_cast<const ulonglong2*>(&As_[buf][k][ty * 16]);
            ulonglong2 av1 = *reinterpret_cast<const ulonglong2*>(&As_[buf][k][ty * 16 + 4]);
            ulonglong2 av2 = *reinterpret_cast<const ulonglong2*>(&As_[buf][k][ty * 16 + 8]);
            ulonglong2 av3 = *reinterpret_cast<const ulonglong2*>(&As_[buf][k][ty * 16 + 12]);
            // B column pairs: (b_{2j}, b_{2j+1}), 2x LDS.128
            ulonglong2 bv0 = *reinterpret_cast<const ulonglong2*>(&Bs_[buf][k][tx * 8]);
            ulonglong2 bv1 = *reinterpret_cast<const ulonglong2*>(&Bs_[buf][k][tx * 8 + 4]);
            unsigned long long a2[8] = {av0.x, av0.y, av1.x, av1.y, av2.x, av2.y, av3.x, av3.y};
            unsigned long long b2[4] = {bv0.x, bv0.y, bv1.x, bv1.y};
            #pragma unroll
            for (int i = 0; i < 8; i++) {
                FFMA2(acc2[i][0], a2[i], b2[0]);
                FFMA2(acc2[i][1], a2[i], b2[1]);
                FFMA2(acc2[i][2], a2[i], b2[2]);
                FFMA2(acc2[i][3], a2[i], b2[3]);
            }
        }
        __syncthreads();
    }

    #pragma unroll
    for (int i = 0; i < 8; i++) {
        int row = row0 + ty * 8 + i;
        if (row < NN) {
            ulonglong2 s0, s1;
            s0.x = acc2[i][0]; s0.y = acc2[i][1];
            s1.x = acc2[i][2]; s1.y = acc2[i][3];
            *reinterpret_cast<ulonglong2*>(g_U + (size_t)row * 256 + col_off + tx * 8) = s0;
            *reinterpret_cast<ulonglong2*>(g_U + (size_t)row * 256 + col_off + tx * 8 + 4) = s1;
        }
    }
}

// ---------------------------------------------------------------
// agg1: x1[n] = relu(U_self[n] + mean_src U_neigh[src] + b0)   (warp per node)
__global__ __launch_bounds__(256) void agg1_kernel(const float* __restrict__ b0v,
                                                   float* __restrict__ xout)
{
    int w = (blockIdx.x * blockDim.x + threadIdx.x) >> 5;
    int lane = threadIdx.x & 31;
    if (w >= NN) return;
    int beg = g_ptr[w], end = g_ptr[w + 1];
    float4 acc = make_float4(0.f, 0.f, 0.f, 0.f);
    for (int e = beg; e < end; e++) {
        int s = g_src[e];
        float4 v = *reinterpret_cast<const float4*>(g_U + (size_t)s * 256 + 128 + lane * 4);
        acc.x += v.x; acc.y += v.y; acc.z += v.z; acc.w += v.w;
    }
    float inv = 1.0f / fmaxf((float)(end - beg), 1.0f);
    float4 self = *reinterpret_cast<const float4*>(g_U + (size_t)w * 256 + lane * 4);
    float4 b = *reinterpret_cast<const float4*>(b0v + lane * 4);
    float4 o;
    o.x = fmaxf(self.x + acc.x * inv + b.x, 0.f);
    o.y = fmaxf(self.y + acc.y * inv + b.y, 0.f);
    o.z = fmaxf(self.z + acc.z * inv + b.z, 0.f);
    o.w = fmaxf(self.w + acc.w * inv + b.w, 0.f);
    *reinterpret_cast<float4*>(xout + (size_t)w * CDIM + lane * 4) = o;
}

// ---------------------------------------------------------------
// fold: Wc = [Ws1 @ Hw | Wn1 @ Hw] (layout [k][32]), bc = b1 @ Hw + Hb
// parallel: blocks 0..31 compute 128 weight entries each; block 32 does bias.
__global__ __launch_bounds__(128) void fold_kernel(
    const float* __restrict__ ws1, const float* __restrict__ wn1,
    const float* __restrict__ b1v,
    const float* __restrict__ hw, const float* __restrict__ hb)
{
    __shared__ float sH[CDIM * NOUT];
    int tid = threadIdx.x;
    for (int i = tid; i < CDIM * NOUT; i += 128) sH[i] = hw[i];
    __syncthreads();

    if (blockIdx.x < 32) {
        int idx = blockIdx.x * 128 + tid;   // 0..4095
        int half = (idx >> 4) & 1;          // 0: self, 1: neigh
        int k = idx >> 5;                   // 0..127
        int j = idx & 15;                   // 0..15
        const float* W = half ? wn1 : ws1;
        float acc = 0.f;
        #pragma unroll 8
        for (int c = 0; c < CDIM; c++)
            acc += W[k * CDIM + c] * sH[c * NOUT + j];
        g_wc[k * 32 + half * 16 + j] = acc;
    } else if (tid < NOUT) {
        float acc = hb[tid];
        for (int c = 0; c < CDIM; c++)
            acc += b1v[c] * sH[c * NOUT + tid];
        g_bc[tid] = acc;
    }
}

// ---------------------------------------------------------------
// GEMM2: V = x1 @ Wc   ([NN,128] @ [128,32]); 64 rows per block, f32x2 packed
__global__ __launch_bounds__(256) void gemm2_kernel(const float* __restrict__ A)
{
    __shared__ __align__(16) float ws[CDIM * 32];   // [k][c]
    __shared__ __align__(16) float xs[64][132];     // padded
    int tid = threadIdx.x;
    for (int i = tid; i < CDIM * 32; i += 256) ws[i] = g_wc[i];

    int base = blockIdx.x * 64;
    #pragma unroll
    for (int p = 0; p < 8; p++) {
        int idx = tid + p * 256;
        int r = idx >> 5;
        int c = (idx & 31) * 4;
        float4 v = make_float4(0.f, 0.f, 0.f, 0.f);
        if (base + r < NN)
            v = *reinterpret_cast<const float4*>(A + (size_t)(base + r) * CDIM + c);
        *reinterpret_cast<float4*>(&xs[r][c]) = v;
    }
    __syncthreads();

    int row = tid >> 2;              // 0..63
    int colg = (tid & 3) * 8;        // 0,8,16,24
    unsigned long long acc2[4] = {0ull, 0ull, 0ull, 0ull};
    #pragma unroll 4
    for (int k = 0; k < CDIM; k++) {
        float xv = xs[row][k];
        unsigned long long x2;
        asm("mov.b64 %0, {%1, %1};" : "=l"(x2) : "f"(xv));
        ulonglong2 w01 = *reinterpret_cast<const ulonglong2*>(&ws[k * 32 + colg]);
        ulonglong2 w23 = *reinterpret_cast<const ulonglong2*>(&ws[k * 32 + colg + 4]);
        FFMA2(acc2[0], x2, w01.x);
        FFMA2(acc2[1], x2, w01.y);
        FFMA2(acc2[2], x2, w23.x);
        FFMA2(acc2[3], x2, w23.y);
    }
    if (base + row < NN) {
        ulonglong2 s0, s1;
        s0.x = acc2[0]; s0.y = acc2[1];
        s1.x = acc2[2]; s1.y = acc2[3];
        *reinterpret_cast<ulonglong2*>(g_V + (size_t)(base + row) * 32 + colg) = s0;
        *reinterpret_cast<ulonglong2*>(g_V + (size_t)(base + row) * 32 + colg + 4) = s1;
    }
}

// ---------------------------------------------------------------
// agg2: out[n][j] = V_self[n][j] + mean_src V_neigh[src][j] + bc[j]
// half-warp per node
__global__ __launch_bounds__(256) void agg2_kernel(float* __restrict__ out)
{
    int w = (blockIdx.x * blockDim.x + threadIdx.x) >> 5;
    int lane = threadIdx.x & 31;
    int n = w * 2 + (lane >> 4);
    int j = lane & 15;
    if (n >= NN) return;
    int beg = g_ptr[n], end = g_ptr[n + 1];
    float acc = 0.f;
    for (int e = beg; e < end; e++) {
        int s = g_src[e];
        acc += g_V[(size_t)s * 32 + 16 + j];
    }
    float inv = 1.0f / fmaxf((float)(end - beg), 1.0f);
    out[(size_t)n * NOUT + j] = g_V[(size_t)n * 32 + j] + acc * inv + g_bc[j];
}

// ---------------------------------------------------------------
extern "C" void kernel_launch(void* const* d_in, const int* in_sizes, int n_in,
                              void* d_out, int out_size)
{
    const float* feats0   = (const float*)d_in[0];
    const float* feats1   = (const float*)d_in[1];
    const float* enc_w0   = (const float*)d_in[2];
    const float* enc_b0   = (const float*)d_in[3];
    const float* enc_w1   = (const float*)d_in[4];
    const float* enc_b1   = (const float*)d_in[5];
    const float* w_self0  = (const float*)d_in[6];
    const float* w_neigh0 = (const float*)d_in[7];
    const float* b0       = (const float*)d_in[8];
    const float* w_self1  = (const float*)d_in[9];
    const float* w_neigh1 = (const float*)d_in[10];
    const float* b1       = (const float*)d_in[11];
    const float* head_w   = (const float*)d_in[12];
    const float* head_b   = (const float*)d_in[13];
    const int*   row_idx  = (const int*)d_in[14];
    const int*   edge_ix  = (const int*)d_in[15];
    float* out = (float*)d_out;

    float* gx;   cudaGetSymbolAddress((void**)&gx,   g_x);
    int*   gcnt; cudaGetSymbolAddress((void**)&gcnt, g_cnt);

    cudaFuncSetAttribute(gemm1_kernel,
                         cudaFuncAttributeMaxDynamicSharedMemorySize, SMEM_GEMM1);

    // CSR build
    cudaMemsetAsync(gcnt, 0, NN * sizeof(int));
    hist_kernel<<<(NE / 4 + 255) / 256, 256>>>(edge_ix);
    scan_kernel<<<1, 1024>>>();
    fill_kernel<<<(NE + 255) / 256, 256>>>(edge_ix);

    // fold layer2+head weights (parallel)
    fold_kernel<<<33, 128>>>(w_self1, w_neigh1, b1, head_w, head_b);

    // encode
    encode_kernel<<<1184, 128>>>(feats0, feats1, enc_w0, enc_b0, enc_w1, enc_b1, row_idx);

    // layer 1: U = x0 @ [Ws0 | Wn0]; x1 = relu(self + mean(neigh) + b0)
    dim3 g1((NN + 127) / 128, 2);
    gemm1_kernel<<<g1, 256, SMEM_GEMM1>>>(gx, w_self0, w_neigh0);
    agg1_kernel<<<(NN * 32 + 255) / 256, 256>>>(b0, gx);

    // layer 2 + head (folded): V = x1 @ Wc; out = self + mean(neigh) + bc
    gemm2_kernel<<<(NN + 63) / 64, 256>>>(gx);
    agg2_kernel<<<(NN * 16 + 255) / 256, 256>>>(out);
}